// round 14
// baseline (speedup 1.0000x reference)
#include <cuda_runtime.h>

// heads: (B=8, H=16, T=4096, D=128) float32
// anchor = head 0, others = heads 1..14, mean over (8,14,4096) of 1 - cos_sim
//
// Roofline-pinned FINAL: 240 MB compulsory zero-reuse reads at the measured
// B300 full-chip load-path cap (~6.2 TB/s, byte-limited; path-independent).
// 38.5 us streaming floor + ~2.5 us ramp/drain.
// Measured: 41.472 us bench x3 consecutive / rel_err 0.0 / 6.16-6.25 TB/s.
// Falsified levers (R2-R12): occupancy up/down, in-flight depth 2-8 f4/lane,
// block 128/256, group width 8/16, tail granularity, L2::256B granularity.
#define B_DIM 8
#define H_DIM 16
#define T_DIM 4096
#define D_DIM 128
#define N_OTHERS 14

#define TASKS_PER_WARP 4            // 4 (b,t) tasks per warp, 8 lanes each
#define WARPS_PER_BLOCK 4
#define THREADS_PER_BLOCK (WARPS_PER_BLOCK * 32)   // 128
#define N_TASKS (B_DIM * T_DIM)                           // 32768
#define N_WARPS (N_TASKS / TASKS_PER_WARP)                // 8192
#define N_BLOCKS (N_WARPS / WARPS_PER_BLOCK)              // 2048
#define N_ROWS_TOTAL (B_DIM * N_OTHERS * T_DIM)           // 458752

// reference: denom = max(sqrt(p), 1e-8)  ==  1/rsqrt(max(p, 1e-16))
#define EPS2 1e-16f

__device__ float g_partials[N_BLOCKS];
__device__ unsigned int g_count = 0;

__device__ __forceinline__ float4 ldcs4(const float4* p) {
    return __ldcs(p);
}

__global__ void __launch_bounds__(THREADS_PER_BLOCK, 5)
cos_dissim_kernel(const float* __restrict__ heads, float* __restrict__ out) {
    const int warp = blockIdx.x * WARPS_PER_BLOCK + (threadIdx.x >> 5);
    const int lane = threadIdx.x & 31;
    const int s    = lane & 7;        // sub-lane within 8-lane group

    const int task = warp * TASKS_PER_WARP + (lane >> 3);
    const int b = task >> 12;                 // task / 4096
    const int t = task & (T_DIM - 1);         // task % 4096

    // Row = 32 float4. Lane s owns float4 indices {s, s+8, s+16, s+24}.
    const float4* base = reinterpret_cast<const float4*>(heads)
                       + (((size_t)b * H_DIM) * T_DIM + t) * (D_DIM / 4) + s;
    const size_t h_stride4 = (size_t)T_DIM * (D_DIM / 4);   // 131072

    // ---- anchor (head 0): 16 floats per lane ----
    float4 a0 = ldcs4(base + 0);
    float4 a1 = ldcs4(base + 8);
    float4 a2 = ldcs4(base + 16);
    float4 a3 = ldcs4(base + 24);

    float na2 = a0.x*a0.x + a0.y*a0.y + a0.z*a0.z + a0.w*a0.w
              + a1.x*a1.x + a1.y*a1.y + a1.z*a1.z + a1.w*a1.w
              + a2.x*a2.x + a2.y*a2.y + a2.z*a2.z + a2.w*a2.w
              + a3.x*a3.x + a3.y*a3.y + a3.z*a3.z + a3.w*a3.w;
    #pragma unroll
    for (int off = 4; off > 0; off >>= 1)
        na2 += __shfl_xor_sync(0xFFFFFFFFu, na2, off);

    // ---- head loop: pairs of heads, 2-pair-deep prefetch (8 float4 in flight) ----
    float local = 0.0f;

    // current pair: heads 1,2
    float4 c0, c1, c2, c3, c4, c5, c6, c7;
    {
        const float4* pA = base + h_stride4;           // head 1
        const float4* pB = base + 2 * h_stride4;       // head 2
        c0 = ldcs4(pA + 0); c1 = ldcs4(pA + 8); c2 = ldcs4(pA + 16); c3 = ldcs4(pA + 24);
        c4 = ldcs4(pB + 0); c5 = ldcs4(pB + 8); c6 = ldcs4(pB + 16); c7 = ldcs4(pB + 24);
    }

    #pragma unroll
    for (int pr = 0; pr < N_OTHERS / 2; pr++) {        // 7 pairs
        float4 n0, n1, n2, n3, n4, n5, n6, n7;
        if (pr < N_OTHERS / 2 - 1) {
            const float4* qA = base + (size_t)(2 * pr + 3) * h_stride4;
            const float4* qB = base + (size_t)(2 * pr + 4) * h_stride4;
            n0 = ldcs4(qA + 0); n1 = ldcs4(qA + 8); n2 = ldcs4(qA + 16); n3 = ldcs4(qA + 24);
            n4 = ldcs4(qB + 0); n5 = ldcs4(qB + 8); n6 = ldcs4(qB + 16); n7 = ldcs4(qB + 24);
        }

        float dotA = c0.x*a0.x + c0.y*a0.y + c0.z*a0.z + c0.w*a0.w
                   + c1.x*a1.x + c1.y*a1.y + c1.z*a1.z + c1.w*a1.w
                   + c2.x*a2.x + c2.y*a2.y + c2.z*a2.z + c2.w*a2.w
                   + c3.x*a3.x + c3.y*a3.y + c3.z*a3.z + c3.w*a3.w;
        float noA  = c0.x*c0.x + c0.y*c0.y + c0.z*c0.z + c0.w*c0.w
                   + c1.x*c1.x + c1.y*c1.y + c1.z*c1.z + c1.w*c1.w
                   + c2.x*c2.x + c2.y*c2.y + c2.z*c2.z + c2.w*c2.w
                   + c3.x*c3.x + c3.y*c3.y + c3.z*c3.z + c3.w*c3.w;
        float dotB = c4.x*a0.x + c4.y*a0.y + c4.z*a0.z + c4.w*a0.w
                   + c5.x*a1.x + c5.y*a1.y + c5.z*a1.z + c5.w*a1.w
                   + c6.x*a2.x + c6.y*a2.y + c6.z*a2.z + c6.w*a2.w
                   + c7.x*a3.x + c7.y*a3.y + c7.z*a3.z + c7.w*a3.w;
        float noB  = c4.x*c4.x + c4.y*c4.y + c4.z*c4.z + c4.w*c4.w
                   + c5.x*c5.x + c5.y*c5.y + c5.z*c5.z + c5.w*c5.w
                   + c6.x*c6.x + c6.y*c6.y + c6.z*c6.z + c6.w*c6.w
                   + c7.x*c7.x + c7.y*c7.y + c7.z*c7.z + c7.w*c7.w;

        // four independent butterfly chains, interleaved to hide SHFL latency
        #pragma unroll
        for (int off = 4; off > 0; off >>= 1) {
            dotA += __shfl_xor_sync(0xFFFFFFFFu, dotA, off);
            noA  += __shfl_xor_sync(0xFFFFFFFFu, noA,  off);
            dotB += __shfl_xor_sync(0xFFFFFFFFu, dotB, off);
            noB  += __shfl_xor_sync(0xFFFFFFFFu, noB,  off);
        }

        local += 2.0f - dotA * rsqrtf(fmaxf(noA * na2, EPS2))
                      - dotB * rsqrtf(fmaxf(noB * na2, EPS2));

        c0 = n0; c1 = n1; c2 = n2; c3 = n3;
        c4 = n4; c5 = n5; c6 = n6; c7 = n7;
    }

    // one copy per task (group leader), fold 4 groups -> lane 0
    if (s != 0) local = 0.0f;
    local += __shfl_xor_sync(0xFFFFFFFFu, local, 8);
    local += __shfl_xor_sync(0xFFFFFFFFu, local, 16);

    __shared__ float s_warp[WARPS_PER_BLOCK];
    __shared__ bool s_is_last;
    if (lane == 0) s_warp[threadIdx.x >> 5] = local;
    __syncthreads();

    if (threadIdx.x == 0) {
        float sum = 0.0f;
        #pragma unroll
        for (int w = 0; w < WARPS_PER_BLOCK; w++) sum += s_warp[w];
        g_partials[blockIdx.x] = sum;
        __threadfence();
        unsigned int old = atomicAdd(&g_count, 1u);
        s_is_last = (old == (unsigned int)(N_BLOCKS - 1));
    }
    __syncthreads();

    // ---- last block folds all partials (fixed order -> deterministic) ----
    if (s_is_last) {
        __shared__ float s_red[THREADS_PER_BLOCK];
        float acc = 0.0f;
        #pragma unroll
        for (int i = threadIdx.x; i < N_BLOCKS; i += THREADS_PER_BLOCK)
            acc += g_partials[i];
        s_red[threadIdx.x] = acc;
        __syncthreads();
        #pragma unroll
        for (int stride = THREADS_PER_BLOCK / 2; stride >= 32; stride >>= 1) {
            if (threadIdx.x < stride) s_red[threadIdx.x] += s_red[threadIdx.x + stride];
            __syncthreads();
        }
        if (threadIdx.x < 32) {
            float v = s_red[threadIdx.x];
            #pragma unroll
            for (int off = 16; off > 0; off >>= 1)
                v += __shfl_xor_sync(0xFFFFFFFFu, v, off);
            if (threadIdx.x == 0) {
                out[0] = v * (1.0f / (float)N_ROWS_TOTAL);
                g_count = 0;   // reset for next graph replay
            }
        }
    }
}

extern "C" void kernel_launch(void* const* d_in, const int* in_sizes, int n_in,
                              void* d_out, int out_size) {
    const float* heads = (const float*)d_in[0];
    float* out = (float*)d_out;
    cos_dissim_kernel<<<N_BLOCKS, THREADS_PER_BLOCK>>>(heads, out);
}

// round 15
// speedup vs baseline: 1.0062x; 1.0062x over previous
#include <cuda_runtime.h>

// heads: (B=8, H=16, T=4096, D=128) float32
// anchor = head 0, others = heads 1..14, mean over (8,14,4096) of 1 - cos_sim
//
// Roofline-pinned FINAL: 240 MB compulsory zero-reuse reads at the measured
// B300 full-chip load-path cap (~6.0-6.25 TB/s run-to-run, byte-limited,
// path-independent). 38.5 us streaming floor + ~2.5 us ramp/drain.
// Measured on this exact binary: 41.472 us x3, 41.696 us x1, rel_err 0.0.
// Falsified levers (R2-R14): occupancy up/down, in-flight depth 2-8 f4/lane,
// block 128/256, group width 8/16, tail granularity, L2::256B granularity.
#define B_DIM 8
#define H_DIM 16
#define T_DIM 4096
#define D_DIM 128
#define N_OTHERS 14

#define TASKS_PER_WARP 4            // 4 (b,t) tasks per warp, 8 lanes each
#define WARPS_PER_BLOCK 4
#define THREADS_PER_BLOCK (WARPS_PER_BLOCK * 32)   // 128
#define N_TASKS (B_DIM * T_DIM)                           // 32768
#define N_WARPS (N_TASKS / TASKS_PER_WARP)                // 8192
#define N_BLOCKS (N_WARPS / WARPS_PER_BLOCK)              // 2048
#define N_ROWS_TOTAL (B_DIM * N_OTHERS * T_DIM)           // 458752

// reference: denom = max(sqrt(p), 1e-8)  ==  1/rsqrt(max(p, 1e-16))
#define EPS2 1e-16f

__device__ float g_partials[N_BLOCKS];
__device__ unsigned int g_count = 0;

__device__ __forceinline__ float4 ldcs4(const float4* p) {
    return __ldcs(p);
}

__global__ void __launch_bounds__(THREADS_PER_BLOCK, 5)
cos_dissim_kernel(const float* __restrict__ heads, float* __restrict__ out) {
    const int warp = blockIdx.x * WARPS_PER_BLOCK + (threadIdx.x >> 5);
    const int lane = threadIdx.x & 31;
    const int s    = lane & 7;        // sub-lane within 8-lane group

    const int task = warp * TASKS_PER_WARP + (lane >> 3);
    const int b = task >> 12;                 // task / 4096
    const int t = task & (T_DIM - 1);         // task % 4096

    // Row = 32 float4. Lane s owns float4 indices {s, s+8, s+16, s+24}.
    const float4* base = reinterpret_cast<const float4*>(heads)
                       + (((size_t)b * H_DIM) * T_DIM + t) * (D_DIM / 4) + s;
    const size_t h_stride4 = (size_t)T_DIM * (D_DIM / 4);   // 131072

    // ---- anchor (head 0): 16 floats per lane ----
    float4 a0 = ldcs4(base + 0);
    float4 a1 = ldcs4(base + 8);
    float4 a2 = ldcs4(base + 16);
    float4 a3 = ldcs4(base + 24);

    float na2 = a0.x*a0.x + a0.y*a0.y + a0.z*a0.z + a0.w*a0.w
              + a1.x*a1.x + a1.y*a1.y + a1.z*a1.z + a1.w*a1.w
              + a2.x*a2.x + a2.y*a2.y + a2.z*a2.z + a2.w*a2.w
              + a3.x*a3.x + a3.y*a3.y + a3.z*a3.z + a3.w*a3.w;
    #pragma unroll
    for (int off = 4; off > 0; off >>= 1)
        na2 += __shfl_xor_sync(0xFFFFFFFFu, na2, off);

    // ---- head loop: pairs of heads, 2-pair-deep prefetch (8 float4 in flight) ----
    float local = 0.0f;

    // current pair: heads 1,2
    float4 c0, c1, c2, c3, c4, c5, c6, c7;
    {
        const float4* pA = base + h_stride4;           // head 1
        const float4* pB = base + 2 * h_stride4;       // head 2
        c0 = ldcs4(pA + 0); c1 = ldcs4(pA + 8); c2 = ldcs4(pA + 16); c3 = ldcs4(pA + 24);
        c4 = ldcs4(pB + 0); c5 = ldcs4(pB + 8); c6 = ldcs4(pB + 16); c7 = ldcs4(pB + 24);
    }

    #pragma unroll
    for (int pr = 0; pr < N_OTHERS / 2; pr++) {        // 7 pairs
        float4 n0, n1, n2, n3, n4, n5, n6, n7;
        if (pr < N_OTHERS / 2 - 1) {
            const float4* qA = base + (size_t)(2 * pr + 3) * h_stride4;
            const float4* qB = base + (size_t)(2 * pr + 4) * h_stride4;
            n0 = ldcs4(qA + 0); n1 = ldcs4(qA + 8); n2 = ldcs4(qA + 16); n3 = ldcs4(qA + 24);
            n4 = ldcs4(qB + 0); n5 = ldcs4(qB + 8); n6 = ldcs4(qB + 16); n7 = ldcs4(qB + 24);
        }

        float dotA = c0.x*a0.x + c0.y*a0.y + c0.z*a0.z + c0.w*a0.w
                   + c1.x*a1.x + c1.y*a1.y + c1.z*a1.z + c1.w*a1.w
                   + c2.x*a2.x + c2.y*a2.y + c2.z*a2.z + c2.w*a2.w
                   + c3.x*a3.x + c3.y*a3.y + c3.z*a3.z + c3.w*a3.w;
        float noA  = c0.x*c0.x + c0.y*c0.y + c0.z*c0.z + c0.w*c0.w
                   + c1.x*c1.x + c1.y*c1.y + c1.z*c1.z + c1.w*c1.w
                   + c2.x*c2.x + c2.y*c2.y + c2.z*c2.z + c2.w*c2.w
                   + c3.x*c3.x + c3.y*c3.y + c3.z*c3.z + c3.w*c3.w;
        float dotB = c4.x*a0.x + c4.y*a0.y + c4.z*a0.z + c4.w*a0.w
                   + c5.x*a1.x + c5.y*a1.y + c5.z*a1.z + c5.w*a1.w
                   + c6.x*a2.x + c6.y*a2.y + c6.z*a2.z + c6.w*a2.w
                   + c7.x*a3.x + c7.y*a3.y + c7.z*a3.z + c7.w*a3.w;
        float noB  = c4.x*c4.x + c4.y*c4.y + c4.z*c4.z + c4.w*c4.w
                   + c5.x*c5.x + c5.y*c5.y + c5.z*c5.z + c5.w*c5.w
                   + c6.x*c6.x + c6.y*c6.y + c6.z*c6.z + c6.w*c6.w
                   + c7.x*c7.x + c7.y*c7.y + c7.z*c7.z + c7.w*c7.w;

        // four independent butterfly chains, interleaved to hide SHFL latency
        #pragma unroll
        for (int off = 4; off > 0; off >>= 1) {
            dotA += __shfl_xor_sync(0xFFFFFFFFu, dotA, off);
            noA  += __shfl_xor_sync(0xFFFFFFFFu, noA,  off);
            dotB += __shfl_xor_sync(0xFFFFFFFFu, dotB, off);
            noB  += __shfl_xor_sync(0xFFFFFFFFu, noB,  off);
        }

        local += 2.0f - dotA * rsqrtf(fmaxf(noA * na2, EPS2))
                      - dotB * rsqrtf(fmaxf(noB * na2, EPS2));

        c0 = n0; c1 = n1; c2 = n2; c3 = n3;
        c4 = n4; c5 = n5; c6 = n6; c7 = n7;
    }

    // one copy per task (group leader), fold 4 groups -> lane 0
    if (s != 0) local = 0.0f;
    local += __shfl_xor_sync(0xFFFFFFFFu, local, 8);
    local += __shfl_xor_sync(0xFFFFFFFFu, local, 16);

    __shared__ float s_warp[WARPS_PER_BLOCK];
    __shared__ bool s_is_last;
    if (lane == 0) s_warp[threadIdx.x >> 5] = local;
    __syncthreads();

    if (threadIdx.x == 0) {
        float sum = 0.0f;
        #pragma unroll
        for (int w = 0; w < WARPS_PER_BLOCK; w++) sum += s_warp[w];
        g_partials[blockIdx.x] = sum;
        __threadfence();
        unsigned int old = atomicAdd(&g_count, 1u);
        s_is_last = (old == (unsigned int)(N_BLOCKS - 1));
    }
    __syncthreads();

    // ---- last block folds all partials (fixed order -> deterministic) ----
    if (s_is_last) {
        __shared__ float s_red[THREADS_PER_BLOCK];
        float acc = 0.0f;
        #pragma unroll
        for (int i = threadIdx.x; i < N_BLOCKS; i += THREADS_PER_BLOCK)
            acc += g_partials[i];
        s_red[threadIdx.x] = acc;
        __syncthreads();
        #pragma unroll
        for (int stride = THREADS_PER_BLOCK / 2; stride >= 32; stride >>= 1) {
            if (threadIdx.x < stride) s_red[threadIdx.x] += s_red[threadIdx.x + stride];
            __syncthreads();
        }
        if (threadIdx.x < 32) {
            float v = s_red[threadIdx.x];
            #pragma unroll
            for (int off = 16; off > 0; off >>= 1)
                v += __shfl_xor_sync(0xFFFFFFFFu, v, off);
            if (threadIdx.x == 0) {
                out[0] = v * (1.0f / (float)N_ROWS_TOTAL);
                g_count = 0;   // reset for next graph replay
            }
        }
    }
}

extern "C" void kernel_launch(void* const* d_in, const int* in_sizes, int n_in,
                              void* d_out, int out_size) {
    const float* heads = (const float*)d_in[0];
    float* out = (float*)d_out;
    cos_dissim_kernel<<<N_BLOCKS, THREADS_PER_BLOCK>>>(heads, out);
}